// round 11
// baseline (speedup 1.0000x reference)
#include <cuda_runtime.h>
#include <cstdint>
#include <math.h>

// Problem shape (fixed by setup_inputs)
#define BB   8
#define HH   256
#define WW   256
#define NPIX (BB * HH * WW)
#define GRID 64           // 8 clusters x 8 CTAs; cluster = one batch image
#define TPB  256
#define CLUSTER 8
#define RPC  32           // rows per CTA

// Persistent scratch (only the ticket needs resetting each launch).
__device__ double   g_part[GRID * 5];
__device__ unsigned g_done;

__device__ __forceinline__ float warp_sum_f(float v) {
    #pragma unroll
    for (int o = 16; o > 0; o >>= 1) v += __shfl_xor_sync(0xffffffffu, v, o);
    return v;
}

__device__ __forceinline__ uint32_t smem_u32(const void* p) {
    uint32_t a;
    asm("{ .reg .u64 t; cvta.to.shared.u64 t, %1; cvt.u32.u64 %0, t; }"
        : "=r"(a) : "l"(p));
    return a;
}

// Read a 32-bit word from a peer CTA's shared memory (same cluster).
__device__ __forceinline__ unsigned dsmem_read_u32(uint32_t local_addr, unsigned rank) {
    uint32_t remote, v;
    asm volatile("mapa.shared::cluster.u32 %0, %1, %2;"
                 : "=r"(remote) : "r"(local_addr), "r"(rank));
    asm volatile("ld.shared::cluster.u32 %0, [%1];" : "=r"(v) : "r"(remote));
    return v;
}

#define CLUSTER_SYNC() do {                                        \
    asm volatile("barrier.cluster.arrive.aligned;" ::: "memory");  \
    asm volatile("barrier.cluster.wait.aligned;" ::: "memory");    \
} while (0)

// ln(1+u) for u in (-0.5, 0], degree-12 Taylor/Horner. |err| < 2e-5 worst case.
__device__ __forceinline__ float ln1p_poly(float u) {
    float s = -1.0f / 12.0f;
    s = fmaf(s, u, 1.0f / 11.0f);
    s = fmaf(s, u, -0.1f);
    s = fmaf(s, u, 1.0f / 9.0f);
    s = fmaf(s, u, -0.125f);
    s = fmaf(s, u, 1.0f / 7.0f);
    s = fmaf(s, u, -1.0f / 6.0f);
    s = fmaf(s, u, 0.2f);
    s = fmaf(s, u, -0.25f);
    s = fmaf(s, u, 1.0f / 3.0f);
    s = fmaf(s, u, -0.5f);
    s = fmaf(s, u, 1.0f);
    return u * s;
}

__global__ void __launch_bounds__(TPB, 1) __cluster_dims__(CLUSTER, 1, 1)
fused_loss_kernel(const float* __restrict__ logits,
                  const float* __restrict__ target,
                  float* __restrict__ out, int out_size)
{
    const int tid  = threadIdx.x;              // = column
    const int bid  = blockIdx.x;
    const int lane = tid & 31, warp = tid >> 5;

    __shared__ float    s_g2[RPC][WW];         // 32 KB
    __shared__ unsigned s_mask[WW];            // this CTA's fg chunk masks
    __shared__ float    s_red[8][5];
    __shared__ int      s_ne;
    __shared__ unsigned s_ticket;

    const int      b    = bid >> 3;            // batch = cluster id
    const unsigned rank = bid & 7;             // row chunk within batch
    const int      r0   = (int)rank * RPC;

    if (tid == 0) s_ne = 0;

    // ===== phase A: load 32 rows, elementwise math, build fg mask ==========
    const float* tb = target + b * HH * WW + tid;
    const float* lb = logits + b * HH * WW + tid;

    unsigned mask = 0;
    float ps[RPC];
    float acc0 = 0.f, acc1 = 0.f, acc2 = 0.f, acc3 = 0.f, acc4 = 0.f;

    #pragma unroll
    for (int i = 0; i < RPC; i++) {
        float t = tb[(r0 + i) * WW];           // coalesced
        float x = lb[(r0 + i) * WW];
        if (t > 0.5f) mask |= (1u << i);
        t = fminf(fmaxf(t, 0.0f), 1.0f);
        float th;
        asm("tanh.approx.f32 %0, %1;" : "=f"(th) : "f"(0.5f * x));
        float h = 0.5f * th;                   // sigmoid(x) = 0.5 + h
        float p = fminf(fmaxf(0.5f + h, 1e-6f), 1.0f - 1e-6f);
        float u = fabsf(h) - 0.5f;             // sigmoid(|x|) - 1
        float ce = fmaxf(x, 0.0f) - ln1p_poly(u) - x * t;
        ps[i] = p;
        acc0 += ce; acc1 += p; acc2 += t; acc3 += p * t;
    }
    s_mask[tid] = mask;
    __syncthreads();
    CLUSTER_SYNC();                            // peer s_mask now visible

    // ===== gather the full column's 8 mask words (7 via DSMEM) =============
    unsigned m[8];
    uint32_t myaddr = smem_u32(&s_mask[0]) + tid * 4;
    #pragma unroll
    for (unsigned wp = 0; wp < 8; wp++)
        m[wp] = (wp == rank) ? mask : dsmem_read_u32(myaddr, wp);
    CLUSTER_SYNC();                            // no peer-smem access after this

    if ((m[0] | m[1] | m[2] | m[3] | m[4] | m[5] | m[6] | m[7]) != 0u)
        s_ne = 1;                              // benign same-value race

    // ===== vertical EDT for own 32 rows (exact reference semantics) ========
    {
        int cin = 512;                         // forward carry into chunk
        #pragma unroll
        for (int wp = 0; wp < 7; wp++) {
            if (wp < (int)rank)
                cin = m[wp] ? __clz((int)m[wp]) : cin + 32;
        }
        int cbk = 512;                         // backward carry into chunk
        #pragma unroll
        for (int wp = 7; wp >= 1; wp--) {
            if (wp > (int)rank)
                cbk = m[wp] ? (__ffs((int)m[wp]) - 1) : cbk + 32;
        }
        int f[RPC];
        int d = cin;
        #pragma unroll
        for (int i = 0; i < RPC; i++) {
            d = ((mask >> i) & 1u) ? 0 : d + 1;
            f[i] = d;
        }
        d = cbk;
        #pragma unroll
        for (int i = RPC - 1; i >= 0; i--) {
            d = ((mask >> i) & 1u) ? 0 : d + 1;
            int g = min(f[i], d);
            s_g2[i][tid] = (float)(g * g);
        }
    }
    __syncthreads();

    // ===== horizontal exact EDT + boundary term ============================
    if (s_ne) {
        #pragma unroll 4
        for (int i = 0; i < RPC; i++) {
            float best = s_g2[i][tid];
            int off = 1;
            float o2 = 1.0f;
            while (o2 < best) {
                int l = tid - off, r = tid + off;
                if (l >= 0) best = fminf(best, o2 + s_g2[i][l]);
                if (r < WW) best = fminf(best, o2 + s_g2[i][r]);
                off++;
                o2 = (float)(off * off);
            }
            float dt = (best <= 1.0f) ? best : sqrtf(best);
            acc4 += ps[i] * dt;
        }
    }

    // ===== per-CTA reduction -> g_part (deterministic) =====================
    {
        float accs[5] = { acc0, acc1, acc2, acc3, acc4 };
        #pragma unroll
        for (int s = 0; s < 5; s++) {
            float v = warp_sum_f(accs[s]);
            if (lane == 0) s_red[warp][s] = v;
        }
        __syncthreads();
        if (warp < 5) {                        // warps 0..4: one scalar each
            float v = (lane < 8) ? s_red[lane][warp] : 0.0f;
            v = warp_sum_f(v);
            if (lane == 0) g_part[bid * 5 + warp] = (double)v;
        }
    }
    __threadfence();
    __syncthreads();

    // ===== completion ticket; last CTA finalizes ===========================
    if (tid == 0) s_ticket = atomicAdd(&g_done, 1u);
    __syncthreads();

    if (s_ticket == GRID - 1) {
        __threadfence();
        double v0 = 0, v1 = 0, v2 = 0, v3 = 0, v4 = 0;
        if (tid < GRID) {
            v0 = g_part[tid * 5 + 0];
            v1 = g_part[tid * 5 + 1];
            v2 = g_part[tid * 5 + 2];
            v3 = g_part[tid * 5 + 3];
            v4 = g_part[tid * 5 + 4];
        }
        #pragma unroll
        for (int o = 16; o > 0; o >>= 1) {
            v0 += __shfl_xor_sync(0xffffffffu, v0, o);
            v1 += __shfl_xor_sync(0xffffffffu, v1, o);
            v2 += __shfl_xor_sync(0xffffffffu, v2, o);
            v3 += __shfl_xor_sync(0xffffffffu, v3, o);
            v4 += __shfl_xor_sync(0xffffffffu, v4, o);
        }
        __shared__ double s_d[TPB / 32][5];
        if (lane == 0) {                       // warps 2..7 contribute zeros
            s_d[warp][0] = v0; s_d[warp][1] = v1; s_d[warp][2] = v2;
            s_d[warp][3] = v3; s_d[warp][4] = v4;
        }
        __syncthreads();
        if (tid == 0) {
            double fsum[5] = {0, 0, 0, 0, 0};
            for (int w = 0; w < TPB / 32; w++)
                for (int s = 0; s < 5; s++) fsum[s] += s_d[w][s];

            const double N = (double)NPIX, S = 1e-6;
            double ce       = fsum[0] / N;
            double dice     = 1.0 - (2.0 * fsum[3] + S) / (fsum[1] + fsum[2] + S);
            double boundary = fsum[4] / N;
            double total    = ce + dice + 0.1 * boundary;

            float vals[4] = { (float)total, (float)ce, (float)dice, (float)boundary };
            for (int i = 0; i < out_size && i < 4; i++) out[i] = vals[i];

            g_done = 0;                        // reset for next graph replay
        }
    }
}

extern "C" void kernel_launch(void* const* d_in, const int* in_sizes, int n_in,
                              void* d_out, int out_size) {
    const float* logits = (const float*)d_in[0];
    const float* target = (const float*)d_in[1];
    (void)in_sizes; (void)n_in;
    fused_loss_kernel<<<GRID, TPB>>>(logits, target, (float*)d_out, out_size);
}

// round 12
// speedup vs baseline: 1.2262x; 1.2262x over previous
#include <cuda_runtime.h>
#include <cstdint>
#include <math.h>

// Problem shape (fixed by setup_inputs)
#define BB   8
#define HH   256
#define WW   256
#define NPIX (BB * HH * WW)
#define NROW (BB * HH)    // 2048
#define GRID 296          // 148 SMs x 2 blocks, all co-resident (verified R4)
#define TPB  256
#define P1B  64           // mask-builder blocks (8 per batch)
#define WPB  29           // workers per batch (29*9 >= 256)
#define RPB  9            // max rows per worker block

// Persistent scratch. Counters/flags reset by the finalizer each launch.
__device__ unsigned g_mask[BB * 8 * WW];  // fg bitmask: [b][rowchunk][col]
__device__ int      g_nonempty[BB];
__device__ unsigned g_cnt[BB];            // per-batch mask-ready counters
__device__ unsigned g_done;               // completion ticket
__device__ double   g_part[GRID * 5];     // per-block partial sums

__device__ __forceinline__ float warp_sum_f(float v) {
    #pragma unroll
    for (int o = 16; o > 0; o >>= 1) v += __shfl_xor_sync(0xffffffffu, v, o);
    return v;
}

__device__ __forceinline__ float sqrt_approx(float x) {
    float r;
    asm("sqrt.approx.f32 %0, %1;" : "=f"(r) : "f"(x));
    return r;
}

__global__ void __launch_bounds__(TPB, 2)
fused_loss_kernel(const float* __restrict__ logits,
                  const float* __restrict__ target,
                  float* __restrict__ out, int out_size)
{
    const int tid  = threadIdx.x;
    const int bid  = blockIdx.x;
    const int lane = tid & 31, warp = tid >> 5;

    __shared__ float    s_g2[RPB][WW];
    __shared__ float    s_red[8][5];
    __shared__ unsigned s_ticket;

    // worker row assignment: never crosses a batch boundary
    const int wrk   = bid - P1B;                     // 0..231 for workers
    const int wb    = (wrk >= 0) ? (wrk / WPB) : 0;  // batch
    const int widx  = (wrk >= 0) ? (wrk - wb * WPB) : 0;
    const int r0    = widx * RPB;                    // row within batch
    const int nrows = (wrk >= 0) ? max(0, min(RPB, HH - r0)) : 0;
    const int grow0 = wb * HH + r0;                  // global row

    float ps[RPB];
    float acc0 = 0.f, acc1 = 0.f, acc2 = 0.f, acc3 = 0.f, acc4 = 0.f;

    if (bid < P1B) {
        // ========= mask builders: load 32 rows, pack, store, release ========
        int b   = bid >> 3;
        int col = ((bid & 7) << 5) + lane;
        int rc0 = warp << 5;
        const float* tp = target + b * HH * WW + col;

        unsigned mask = 0;
        #pragma unroll
        for (int i = 0; i < 32; i++) {
            float tv = tp[(rc0 + i) * WW];           // 32 independent loads
            if (tv > 0.5f) mask |= (1u << i);
        }
        g_mask[(b * 8 + warp) * WW + col] = mask;    // coalesced
        if (__any_sync(0xffffffffu, mask != 0u) && lane == 0)
            g_nonempty[b] = 1;                       // benign same-value race
        __threadfence();                             // release masks
        __syncthreads();
        if (tid == 0) atomicAdd(&g_cnt[b], 1u);
    } else if (nrows > 0) {
        // ========= workers: elementwise piece first (overlaps builders) =====
        float xs[RPB], ts[RPB];
        #pragma unroll
        for (int i = 0; i < RPB; i++) {
            if (i < nrows) {
                int idx = (grow0 + i) * WW + tid;
                xs[i] = logits[idx];
                ts[i] = target[idx];
            }
        }
        #pragma unroll
        for (int i = 0; i < RPB; i++) {
            if (i < nrows) {
                float x = xs[i];
                float t = fminf(fmaxf(ts[i], 0.0f), 1.0f);
                float th;
                asm("tanh.approx.f32 %0, %1;" : "=f"(th) : "f"(0.5f * x));
                float h = 0.5f * th;                 // sigmoid(x) = 0.5 + h
                float p = fminf(fmaxf(0.5f + h, 1e-6f), 1.0f - 1e-6f);
                float r = 0.5f + fabsf(h);           // sigmoid(|x|)
                // log1p(e^{-|x|}) = -ln(sigmoid(|x|)) = -ln2*log2(r)
                float ce = fmaxf(x, 0.0f) - 0.69314718055994531f * __log2f(r)
                         - x * t;
                ps[i] = p;
                acc0 += ce; acc1 += p; acc2 += t; acc3 += p * t;
            }
        }

        // ========= acquire this batch's masks (usually already ready) =======
        if (tid == 0) {
            volatile unsigned* vc = &g_cnt[wb];
            while (*vc < 8u) __nanosleep(32);
        }
        __syncthreads();
        __threadfence();

        // load this column's 8 mask words (coalesced, L2-hot)
        unsigned m[8];
        #pragma unroll
        for (int wp = 0; wp < 8; wp++)
            m[wp] = g_mask[(wb * 8 + wp) * WW + tid];

        // ========= vertical distances (exact reference semantics) ==========
        int fwdA[RPB], bwdA[RPB];
        {
            int r = r0, w = r >> 5, bit = r & 31;
            int best_lo = -513;
            #pragma unroll
            for (int wp = 0; wp < 8; wp++) {
                unsigned mm = m[wp];
                if (wp > w) mm = 0;
                else if (wp == w) mm &= (0xffffffffu >> (31 - bit));
                if (mm) best_lo = (wp << 5) + 31 - __clz(mm);
            }
            int f = r - best_lo;
            fwdA[0] = f;
            #pragma unroll
            for (int i = 1; i < RPB; i++) {
                if (i < nrows) {
                    int rr = r0 + i;
                    f = ((m[rr >> 5] >> (rr & 31)) & 1u) ? 0 : f + 1;
                    fwdA[i] = f;
                }
            }
        }
        {
            int re = r0 + nrows - 1, w = re >> 5, bit = re & 31;
            int best_hi = 768;
            #pragma unroll
            for (int wp = 7; wp >= 0; wp--) {
                unsigned mm = m[wp];
                if (wp < w) mm = 0;
                else if (wp == w) mm &= (0xffffffffu << bit);
                if (mm) best_hi = (wp << 5) + __ffs(mm) - 1;
            }
            int bw = best_hi - re;
            bwdA[nrows - 1] = bw;
            #pragma unroll
            for (int i = RPB - 2; i >= 0; i--) {
                if (i < nrows - 1) {
                    int rr = r0 + i;
                    bw = ((m[rr >> 5] >> (rr & 31)) & 1u) ? 0 : bw + 1;
                    bwdA[i] = bw;
                }
            }
        }

        float g2s[RPB];
        #pragma unroll
        for (int i = 0; i < RPB; i++) {
            if (i < nrows) {
                int g = min(fwdA[i], bwdA[i]);
                g2s[i] = (float)(g * g);
                s_g2[i][tid] = g2s[i];
            }
        }
        __syncthreads();

        // ========= exact horizontal EDT + boundary term =====================
        int ne = g_nonempty[wb];
        #pragma unroll
        for (int i = 0; i < RPB; i++) {
            if (i < nrows) {
                float dt = 0.0f;
                if (ne) {
                    float best = g2s[i];
                    int off = 1;
                    float o2 = 1.0f;
                    while (o2 < best) {
                        int l = tid - off, r = tid + off;
                        if (l >= 0) best = fminf(best, o2 + s_g2[i][l]);
                        if (r < WW) best = fminf(best, o2 + s_g2[i][r]);
                        off++;
                        o2 = (float)(off * off);
                    }
                    dt = (best <= 1.0f) ? best : sqrt_approx(best);
                }
                acc4 += ps[i] * dt;
            }
        }
    }

    // ========== per-block reduction -> g_part (deterministic) ===============
    {
        float accs[5] = { acc0, acc1, acc2, acc3, acc4 };
        #pragma unroll
        for (int s = 0; s < 5; s++) {
            float v = warp_sum_f(accs[s]);
            if (lane == 0) s_red[warp][s] = v;
        }
        __syncthreads();
        if (warp < 5) {                  // warps 0..4 reduce one scalar each
            float v = (lane < 8) ? s_red[lane][warp] : 0.0f;
            v = warp_sum_f(v);
            if (lane == 0) g_part[bid * 5 + warp] = (double)v;
        }
    }
    __threadfence();
    __syncthreads();

    // ========== completion ticket; last block finalizes =====================
    if (tid == 0) s_ticket = atomicAdd(&g_done, 1u);
    __syncthreads();

    if (s_ticket == GRID - 1) {
        __threadfence();
        double v0 = 0, v1 = 0, v2 = 0, v3 = 0, v4 = 0;
        for (int i = tid; i < GRID; i += TPB) {
            v0 += g_part[i * 5 + 0];
            v1 += g_part[i * 5 + 1];
            v2 += g_part[i * 5 + 2];
            v3 += g_part[i * 5 + 3];
            v4 += g_part[i * 5 + 4];
        }
        #pragma unroll
        for (int o = 16; o > 0; o >>= 1) {
            v0 += __shfl_xor_sync(0xffffffffu, v0, o);
            v1 += __shfl_xor_sync(0xffffffffu, v1, o);
            v2 += __shfl_xor_sync(0xffffffffu, v2, o);
            v3 += __shfl_xor_sync(0xffffffffu, v3, o);
            v4 += __shfl_xor_sync(0xffffffffu, v4, o);
        }
        __shared__ double s_d[TPB / 32][5];
        if (lane == 0) {
            s_d[warp][0] = v0; s_d[warp][1] = v1; s_d[warp][2] = v2;
            s_d[warp][3] = v3; s_d[warp][4] = v4;
        }
        __syncthreads();
        if (tid == 0) {
            double fsum[5] = {0, 0, 0, 0, 0};
            for (int w = 0; w < TPB / 32; w++)
                for (int s = 0; s < 5; s++) fsum[s] += s_d[w][s];

            const double N = (double)NPIX, S = 1e-6;
            double ce       = fsum[0] / N;
            double dice     = 1.0 - (2.0 * fsum[3] + S) / (fsum[1] + fsum[2] + S);
            double boundary = fsum[4] / N;
            double total    = ce + dice + 0.1 * boundary;

            float vals[4] = { (float)total, (float)ce, (float)dice, (float)boundary };
            for (int i = 0; i < out_size && i < 4; i++) out[i] = vals[i];

            // reset persistent state for next graph replay
            g_done = 0;
            for (int b = 0; b < BB; b++) { g_nonempty[b] = 0; g_cnt[b] = 0; }
        }
    }
}

extern "C" void kernel_launch(void* const* d_in, const int* in_sizes, int n_in,
                              void* d_out, int out_size) {
    const float* logits = (const float*)d_in[0];
    const float* target = (const float*)d_in[1];
    (void)in_sizes; (void)n_in;
    fused_loss_kernel<<<GRID, TPB>>>(logits, target, (float*)d_out, out_size);
}